// round 2
// baseline (speedup 1.0000x reference)
#include <cuda_runtime.h>

// KNN entropy estimator, collapsed form.
// Key identity: kth-smallest_j (x[i,c] - x[j,c]) = x[i,c] - (k+1)-th-largest_j x[j,c],
// so the per-(i,c) selection reduces to one per-column order statistic m_c.
//
// H = -digamma(k) + digamma(D) + (D-1)/k + (1/N) * sum_{i,c} (hi - lo)
//   hi = min(x + (x - m_c), 1),  lo = max(x - (x - m_c), 0)

#define NN 2048
#define DD 16
#define TPB 512                       // 16 warps: one warp per column
#define SMEM_BYTES (NN*DD*4 + DD*4 + TPB*4)

// Branchless insert of v into descending sorted t[0..5] (drops the smallest).
__device__ __forceinline__ void insert6(float t[6], float v) {
#pragma unroll
    for (int j = 0; j < 6; j++) {
        float mx = fmaxf(t[j], v);
        v = fminf(t[j], v);
        t[j] = mx;
    }
}

extern "C" __global__ void knn_entropy_kernel(const float* __restrict__ x,
                                              const int* __restrict__ kptr,
                                              float* __restrict__ out) {
    extern __shared__ float smem[];
    float* sxt = smem;                 // [DD][NN] transposed copy of x
    float* sm  = smem + NN * DD;       // [DD] per-column (k+1)-th largest
    float* red = sm + DD;              // [TPB] block reduction buffer

    const int tid = threadIdx.x;

    // ---- Stage x into SMEM, transposing to column-major [DD][NN] ----
    const float4* x4 = (const float4*)x;
#pragma unroll
    for (int q = tid; q < (NN * DD / 4); q += TPB) {
        float4 f = x4[q];
        int i  = q >> 2;          // row index
        int cb = (q & 3) << 2;    // column base
        sxt[(cb + 0) * NN + i] = f.x;
        sxt[(cb + 1) * NN + i] = f.y;
        sxt[(cb + 2) * NN + i] = f.z;
        sxt[(cb + 3) * NN + i] = f.w;
    }
    __syncthreads();

    const int k = *kptr;          // = 5 in the dataset; generic for k <= 5

    // ---- Per-column top-6 selection: warp w owns column w ----
    const int w    = tid >> 5;
    const int lane = tid & 31;
    float t[6];
#pragma unroll
    for (int j = 0; j < 6; j++) t[j] = -1e30f;

    const float* col = sxt + w * NN;
    for (int i = lane; i < NN; i += 32)   // conflict-free: lane-consecutive addrs
        insert6(t, col[i]);

    // shfl-down tree merge. SNAPSHOT the neighbor's full list BEFORE mutating
    // our own — inserting while shuffling races against the neighbor's own
    // inserts (the R1 bug: 5e-3 rel_err from polluted merges).
#pragma unroll
    for (int off = 16; off >= 1; off >>= 1) {
        float ov[6];
#pragma unroll
        for (int e = 0; e < 6; e++)
            ov[e] = __shfl_down_sync(0xffffffffu, t[e], off);
#pragma unroll
        for (int e = 0; e < 6; e++)
            insert6(t, ov[e]);
    }
    if (lane == 0) {
        float kth;
        if      (k <= 0) kth = t[0];
        else if (k == 1) kth = t[1];
        else if (k == 2) kth = t[2];
        else if (k == 3) kth = t[3];
        else if (k == 4) kth = t[4];
        else             kth = t[5];   // k == 5 path used by the dataset
        sm[w] = kth;
    }
    __syncthreads();

    // ---- Elementwise eps sum over all N*D elements (reads hit SMEM) ----
    float acc = 0.0f;
    for (int f = tid; f < NN * DD; f += TPB) {
        int   c  = f >> 11;            // NN == 2048 == 2^11
        float v  = sxt[f];
        float kd = v - sm[c];
        float hi = fminf(v + kd, 1.0f);
        float lo = fmaxf(v - kd, 0.0f);
        acc += hi - lo;
    }
    red[tid] = acc;
    __syncthreads();

    // Deterministic tree reduction (no float atomics -> bitwise reproducible)
#pragma unroll
    for (int s = TPB / 2; s > 0; s >>= 1) {
        if (tid < s) red[tid] += red[tid + s];
        __syncthreads();
    }

    if (tid == 0) {
        const float GAMMA = 0.57721566490153286f;
        float dig_k = -GAMMA;                       // digamma(k) = -gamma + H_{k-1}
        for (int j = 1; j < k; j++)  dig_k += 1.0f / (float)j;
        float dig_d = -GAMMA;                       // digamma(16)
        for (int j = 1; j < DD; j++) dig_d += 1.0f / (float)j;
        float H = -dig_k + dig_d + (float)(DD - 1) / (float)k + red[0] / (float)NN;
        out[0] = H;
    }
}

extern "C" void kernel_launch(void* const* d_in, const int* in_sizes, int n_in,
                              void* d_out, int out_size) {
    // metadata order: x [N*D f32], k [1 i32] — pick by size to be robust.
    int xi = 0, ki = 1;
    if (n_in >= 2 && in_sizes[0] == 1) { xi = 1; ki = 0; }
    const float* x    = (const float*)d_in[xi];
    const int*   kptr = (const int*)d_in[ki];
    float*       out  = (float*)d_out;

    cudaFuncSetAttribute(knn_entropy_kernel,
                         cudaFuncAttributeMaxDynamicSharedMemorySize, SMEM_BYTES);
    knn_entropy_kernel<<<1, TPB, SMEM_BYTES>>>(x, kptr, out);
}

// round 3
// speedup vs baseline: 1.4579x; 1.4579x over previous
#include <cuda_runtime.h>

// KNN entropy estimator, fully collapsed:
//   kth-smallest_j (x[i,c]-x[j,c]) = x[i,c] - m_c,  m_c = (k+1)-th largest of column c
//   hi = min(2x - m_c, 1),  lo = max(m_c, 0)   (lo is x-independent!)
//   H  = -digamma(k) + digamma(D) + (D-1)/k + (1/N) * sum_{i,c}(hi - lo)
//
// One CTA per column (16 CTAs, 512 thr): values live in registers for both the
// top-6 selection and the eps sum. Last-arriving CTA finalizes via a device
// counter (reset each call -> graph-replay safe, no second launch).

#define NN  2048
#define DD  16
#define TPB 512
#define EPT (NN / TPB)        // 4 elements per thread

__device__ float g_partial[DD];
__device__ int   g_count = 0;

// Branchless insert of v into descending sorted t[0..5] (drops the smallest).
__device__ __forceinline__ void insert6(float t[6], float v) {
#pragma unroll
    for (int j = 0; j < 6; j++) {
        float mx = fmaxf(t[j], v);
        v = fminf(t[j], v);
        t[j] = mx;
    }
}

// Warp top-6 merge: snapshot neighbor's list BEFORE inserting (no pollution).
// Only lane 0's result is valid afterward (standard shfl-down tree validity).
__device__ __forceinline__ void warp_merge6(float t[6]) {
#pragma unroll
    for (int off = 16; off >= 1; off >>= 1) {
        float ov[6];
#pragma unroll
        for (int e = 0; e < 6; e++)
            ov[e] = __shfl_down_sync(0xffffffffu, t[e], off);
#pragma unroll
        for (int e = 0; e < 6; e++)
            insert6(t, ov[e]);
    }
}

extern "C" __global__ void knn_entropy_kernel(const float* __restrict__ x,
                                              const int* __restrict__ kptr,
                                              float* __restrict__ out) {
    __shared__ float wm[16 * 6];     // per-warp top-6 lists
    __shared__ float rsum[16];       // per-warp eps partial sums
    __shared__ float mc_sh;

    const int c    = blockIdx.x;     // column owned by this CTA
    const int tid  = threadIdx.x;
    const int w    = tid >> 5;
    const int lane = tid & 31;
    const int k    = *kptr;          // = 5 in dataset; generic for k <= 5

    // ---- Load this column's elements into registers (strided, L2-shared) ----
    float v[EPT];
#pragma unroll
    for (int r = 0; r < EPT; r++)
        v[r] = x[(r * TPB + tid) * DD + c];

    // ---- Per-lane top-6, then warp merge ----
    float t[6];
#pragma unroll
    for (int j = 0; j < 6; j++) t[j] = -1e30f;
#pragma unroll
    for (int r = 0; r < EPT; r++) insert6(t, v[r]);

    warp_merge6(t);
    if (lane == 0) {
#pragma unroll
        for (int e = 0; e < 6; e++) wm[w * 6 + e] = t[e];
    }
    __syncthreads();

    // ---- Warp 0 merges the 16 per-warp lists (96 values, 3 per lane) ----
    if (w == 0) {
        float t2[6];
#pragma unroll
        for (int j = 0; j < 6; j++) t2[j] = -1e30f;
#pragma unroll
        for (int j = 0; j < 3; j++) insert6(t2, wm[lane * 3 + j]);
        warp_merge6(t2);
        if (lane == 0) {
            int kk = k < 0 ? 0 : (k > 5 ? 5 : k);
            float kth = t2[0];
#pragma unroll
            for (int j = 1; j < 6; j++) if (j == kk) kth = t2[j];
            mc_sh = kth;
        }
    }
    __syncthreads();
    const float mc = mc_sh;

    // ---- eps sum for this column: values still in registers ----
    const float lo = fmaxf(mc, 0.0f);
    float acc = 0.0f;
#pragma unroll
    for (int r = 0; r < EPT; r++)
        acc += fminf(v[r] + (v[r] - mc), 1.0f) - lo;

    // warp sum, then 16-warp sum in warp 0 (fixed order -> deterministic)
#pragma unroll
    for (int off = 16; off >= 1; off >>= 1)
        acc += __shfl_down_sync(0xffffffffu, acc, off);
    if (lane == 0) rsum[w] = acc;
    __syncthreads();

    if (w == 0) {
        float a = (lane < 16) ? rsum[lane] : 0.0f;
#pragma unroll
        for (int off = 8; off >= 1; off >>= 1)
            a += __shfl_down_sync(0xffffffffu, a, off);

        if (lane == 0) {
            g_partial[c] = a;
            __threadfence();
            int done = atomicAdd(&g_count, 1);
            if (done == DD - 1) {            // last CTA finalizes
                __threadfence();
                float s = 0.0f;
#pragma unroll
                for (int c2 = 0; c2 < DD; c2++)
                    s += *((volatile float*)&g_partial[c2]);

                const float GAMMA = 0.57721566490153286f;
                float dig_k = -GAMMA;        // digamma(k) = -gamma + H_{k-1}
                for (int j = 1; j < k; j++)  dig_k += 1.0f / (float)j;
                float dig_d = -GAMMA;        // digamma(D)
                for (int j = 1; j < DD; j++) dig_d += 1.0f / (float)j;
                out[0] = -dig_k + dig_d + (float)(DD - 1) / (float)k
                         + s / (float)NN;

                g_count = 0;                 // reset for next graph replay
            }
        }
    }
}

extern "C" void kernel_launch(void* const* d_in, const int* in_sizes, int n_in,
                              void* d_out, int out_size) {
    // metadata order: x [N*D f32], k [1 i32] — pick by size to be robust.
    int xi = 0, ki = 1;
    if (n_in >= 2 && in_sizes[0] == 1) { xi = 1; ki = 0; }
    const float* x    = (const float*)d_in[xi];
    const int*   kptr = (const int*)d_in[ki];
    float*       out  = (float*)d_out;

    knn_entropy_kernel<<<DD, TPB>>>(x, kptr, out);
}

// round 4
// speedup vs baseline: 1.6479x; 1.1303x over previous
#include <cuda_runtime.h>

// KNN entropy estimator, slab-parallel collapsed form.
//   mc_c = (k+1)-th largest of column c  (selection over column multiset, incl. self)
//   eps_i = min(2x - mc, 1) - max(mc, 0)
//   Sum identity: clippers (x > tau = (1+mc)/2 > mc) are inside the global top-6, so
//     sum_i min(2x-mc,1) = 2*S_c - N*mc - sum_{t in top6, t>tau}(2t - mc - 1)
//   -> slab CTAs only produce (per-column top-6, per-column sum); last CTA combines.
//
// 16 CTAs x 512 thr. CTA b loads rows [128b,128b+128) as one float4/thread
// (fully coalesced, 4 lines/warp), SMEM-transposes, warp w selects column w.
// Merges use bitonic top-6 split + optimal 12-CE sort6 network (depth 5).

#define NN  2048
#define DD  16
#define TPB 512
#define SLABS 16
#define CSTRIDE 129          // padded column stride in smem
#define NEGF (-1e30f)

__device__ float g_top[SLABS][DD][6];
__device__ float g_S[SLABS][DD];
__device__ int   g_count = 0;

__device__ __forceinline__ void ce(float& a, float& b) {   // descending comparator
    float h = fmaxf(a, b), l = fminf(a, b); a = h; b = l;
}

// Optimal 6-element sorting network (12 CE, depth 5), descending.
__device__ __forceinline__ void sort6(float t[6]) {
    ce(t[0],t[5]); ce(t[1],t[3]); ce(t[2],t[4]);
    ce(t[1],t[2]); ce(t[3],t[4]);
    ce(t[0],t[3]); ce(t[2],t[5]);
    ce(t[0],t[1]); ce(t[2],t[3]); ce(t[4],t[5]);
    ce(t[1],t[2]); ce(t[3],t[4]);
}

// Merge two descending 6-lists, keep top-6 (bitonic split: 6 parallel fmax + sort6).
__device__ __forceinline__ void merge6(float t[6], const float o[6]) {
    t[0]=fmaxf(t[0],o[5]); t[1]=fmaxf(t[1],o[4]); t[2]=fmaxf(t[2],o[3]);
    t[3]=fmaxf(t[3],o[2]); t[4]=fmaxf(t[4],o[1]); t[5]=fmaxf(t[5],o[0]);
    sort6(t);
}

template<int FIRST_OFF>
__device__ __forceinline__ void warp_merge6(float t[6]) {
#pragma unroll
    for (int off = FIRST_OFF; off >= 1; off >>= 1) {
        float o[6];
#pragma unroll
        for (int e = 0; e < 6; e++)
            o[e] = __shfl_down_sync(0xffffffffu, t[e], off);
        merge6(t, o);
    }
}

extern "C" __global__ void knn_entropy_kernel(const float* __restrict__ x,
                                              const int* __restrict__ kptr,
                                              float* __restrict__ out) {
    __shared__ float sxt[DD * CSTRIDE];   // transposed slab [col][row(128)+pad]
    __shared__ float colv[DD];
    __shared__ int   sflag;

    const int b    = blockIdx.x;
    const int tid  = threadIdx.x;
    const int w    = tid >> 5;
    const int lane = tid & 31;

    // ---- Coalesced slab load: one float4 per thread (rows 128b .. 128b+127) ----
    float4 f = ((const float4*)x)[b * TPB + tid];
    const int rowl = tid >> 2;            // row within slab, 0..127
    const int c0   = (tid & 3) << 2;      // 4 adjacent columns
    sxt[(c0 + 0) * CSTRIDE + rowl] = f.x;
    sxt[(c0 + 1) * CSTRIDE + rowl] = f.y;
    sxt[(c0 + 2) * CSTRIDE + rowl] = f.z;
    sxt[(c0 + 3) * CSTRIDE + rowl] = f.w;
    __syncthreads();

    // ---- Warp w: slab top-6 + slab sum of column w ----
    const float* col = sxt + w * CSTRIDE;
    float v0 = col[lane], v1 = col[lane + 32], v2 = col[lane + 64], v3 = col[lane + 96];
    float s = (v0 + v1) + (v2 + v3);

    ce(v0, v2); ce(v1, v3); ce(v0, v1); ce(v2, v3); ce(v1, v2);   // sort4 desc
    float t[6] = { v0, v1, v2, v3, NEGF, NEGF };
    warp_merge6<16>(t);
#pragma unroll
    for (int off = 16; off >= 1; off >>= 1)
        s += __shfl_down_sync(0xffffffffu, s, off);

    if (lane == 0) {
#pragma unroll
        for (int e = 0; e < 6; e++) g_top[b][w][e] = t[e];
        g_S[b][w] = s;
    }
    __syncthreads();

    if (tid == 0) {
        __threadfence();
        sflag = (atomicAdd(&g_count, 1) == SLABS - 1);
    }
    __syncthreads();
    if (!sflag) return;

    // ================= last CTA: combine =================
    __threadfence();
    const int k  = *kptr;
    const int kk = k < 0 ? 0 : (k > 5 ? 5 : k);

    // Warp c merges the 16 slab lists + sums for column c (lane i = slab i).
    const int c = w;
    float t2[6];
    float s2 = 0.0f;
    if (lane < SLABS) {
        volatile float* vt = (volatile float*)&g_top[lane][c][0];
#pragma unroll
        for (int e = 0; e < 6; e++) t2[e] = vt[e];
        s2 = *((volatile float*)&g_S[lane][c]);
    } else {
#pragma unroll
        for (int e = 0; e < 6; e++) t2[e] = NEGF;
    }
    warp_merge6<8>(t2);
#pragma unroll
    for (int off = 8; off >= 1; off >>= 1)
        s2 += __shfl_down_sync(0xffffffffu, s2, off);

    if (lane == 0) {
        float mc  = t2[0];
#pragma unroll
        for (int j = 1; j < 6; j++) if (j == kk) mc = t2[j];
        float tau  = 0.5f * (1.0f + mc);
        float corr = 0.0f;
#pragma unroll
        for (int e = 0; e < 6; e++)
            if (t2[e] > tau) corr += 2.0f * t2[e] - mc - 1.0f;
        colv[c] = 2.0f * s2 - (float)NN * mc - corr - (float)NN * fmaxf(mc, 0.0f);
    }
    __syncthreads();

    if (w == 0) {
        float a = (lane < DD) ? colv[lane] : 0.0f;
#pragma unroll
        for (int off = 8; off >= 1; off >>= 1)
            a += __shfl_down_sync(0xffffffffu, a, off);
        if (lane == 0) {
            const float GAMMA = 0.57721566490153286f;
            float dig_k = -GAMMA;                      // digamma(k) = -gamma + H_{k-1}
            for (int j = 1; j < k; j++)  dig_k += 1.0f / (float)j;
            float dig_d = -GAMMA;                      // digamma(D)
            for (int j = 1; j < DD; j++) dig_d += 1.0f / (float)j;
            out[0] = -dig_k + dig_d + (float)(DD - 1) / (float)k + a / (float)NN;
            g_count = 0;                               // reset for next graph replay
        }
    }
}

extern "C" void kernel_launch(void* const* d_in, const int* in_sizes, int n_in,
                              void* d_out, int out_size) {
    // metadata order: x [N*D f32], k [1 i32] — pick by size to be robust.
    int xi = 0, ki = 1;
    if (n_in >= 2 && in_sizes[0] == 1) { xi = 1; ki = 0; }
    const float* x    = (const float*)d_in[xi];
    const int*   kptr = (const int*)d_in[ki];
    float*       out  = (float*)d_out;

    knn_entropy_kernel<<<SLABS, TPB>>>(x, kptr, out);
}